// round 15
// baseline (speedup 1.0000x reference)
#include <cuda_runtime.h>
#include <cuda_fp16.h>
#include <cstdint>

#define NUM_DST   10000
#define NUM_EDGES 600000
#define DN   100
#define DE   172
#define DTF  100
#define DOUT 128
#define KDIM (DN + DE + DTF)   // 372
#define NPC  6                 // k-pair chunks: k = it*64 + lane*2

// ---------------- scratch ----------------------------------------------------
__device__ float   g_qbk[NUM_DST * 2];
__device__ __half2 g_Pqh[(size_t)NUM_DST * KDIM];   // [d][k] -> (head0, head1) fp16
__device__ float2  g_U[(size_t)NUM_DST * KDIM];     // [d][k] -> (head0, head1) fp32
__device__ float   g_z[NUM_DST * 2];
__device__ float   g_qbias[DOUT];
__device__ float   g_absum[2];

#define U_FLOAT4 ((NUM_DST * KDIM * 2) / 4)   // 1,860,000
#define Z_FLOAT4 ((NUM_DST * 2) / 4)          // 5,000

// pqfused dynamic smem layout (bytes)
#define PQ_QS   (128 * 68 * 4)                // 34816
#define PQ_AS   (128 * 68 * 4)                // 34816
#define PQ_BS   (64 * 136 * 4)                // 34816
#define PQ_SMEM (PQ_QS + PQ_AS + PQ_BS)       // 104448

__device__ __forceinline__ uint32_t to_tf32(float f) {
    uint32_t r;
    asm("cvt.rna.tf32.f32 %0, %1;" : "=r"(r) : "f"(f));
    return r;
}

// ---------------- kernel 0: init (vectorized zero) + derived constants -------
__global__ void init_kernel(const float* __restrict__ time_b,
                            const float* __restrict__ wq,
                            const float* __restrict__ bq,
                            const float* __restrict__ att_bias)
{
    int idx = blockIdx.x * blockDim.x + threadIdx.x;
    float4 zero4 = make_float4(0.f, 0.f, 0.f, 0.f);
    if (idx < U_FLOAT4) ((float4*)g_U)[idx] = zero4;
    if (idx < Z_FLOAT4) ((float4*)g_z)[idx] = zero4;
    if (idx < DOUT) {
        float acc = bq[idx];
        #pragma unroll 4
        for (int t = 0; t < DTF; t++)
            acc += cosf(time_b[t]) * wq[(DN + t) * DOUT + idx];
        g_qbias[idx] = acc;
    }
    if (idx < 2) {
        float s = 0.f;
        for (int j = 0; j < DOUT / 2; j++) s += att_bias[idx * (DOUT / 2) + j];
        g_absum[idx] = s;
    }
}

// ---------------- kernel 1: fused q + Pq via tf32 MMA ------------------------
// Stage 1: q[d, c] = sum_j h[d,j]*wq[j, 64hh+c] + qbias (K=100, 2 chunks).
// Stage 2: Pq_hh[d, k] = sum_c q[d,c]*wk[k, 64hh+c]  (K=64, verified layout).
// kbase==0 blocks also write qbk[d,hh] = sum_c q[d,c]*bk[64hh+c].
__global__ __launch_bounds__(256) void pqfused_kernel(
    const float* __restrict__ h,  const float* __restrict__ wq,
    const float* __restrict__ wk, const float* __restrict__ bk)
{
    extern __shared__ char sm_[];
    float (*qs)[68]  = (float(*)[68])sm_;
    float (*As)[68]  = (float(*)[68])(sm_ + PQ_QS);
    float (*Bs)[136] = (float(*)[136])(sm_ + PQ_QS + PQ_AS);

    const int dbase = blockIdx.x * 128;
    const int kbase = blockIdx.y * 128;
    const int hh    = blockIdx.z;
    const int tid  = threadIdx.x;
    const int lane = tid & 31;
    const int wid  = tid >> 5;
    const int wm   = wid & 3;
    const int wn   = wid >> 2;

    // ---- stage 1: q-tile via MMA, K=100 in 2 chunks of 64 ----
    float acc1[2][4][4];
    #pragma unroll
    for (int mf = 0; mf < 2; mf++)
        #pragma unroll
        for (int nf = 0; nf < 4; nf++)
            #pragma unroll
            for (int r = 0; r < 4; r++) acc1[mf][nf][r] = 0.f;

    #pragma unroll 1
    for (int kc = 0; kc < 2; kc++) {
        for (int i = tid; i < 128 * 64; i += 256) {
            int r = i >> 6, c = i & 63;
            int j = kc * 64 + c;
            int d = dbase + r;
            float vv = (d < NUM_DST && j < DN) ? h[(size_t)d * DN + j] : 0.f;
            As[r][c] = __uint_as_float(to_tf32(vv));
        }
        for (int i = tid; i < 64 * 64; i += 256) {
            int c = i >> 6, n = i & 63;
            int j = kc * 64 + c;
            float vv = (j < DN) ? wq[j * DOUT + hh * 64 + n] : 0.f;
            Bs[c][n] = __uint_as_float(to_tf32(vv));
        }
        __syncthreads();
        #pragma unroll
        for (int ks = 0; ks < 8; ks++) {
            int acol = (lane & 3) + ks * 8;
            uint32_t a[2][4];
            #pragma unroll
            for (int mf = 0; mf < 2; mf++) {
                int rb = wm * 32 + mf * 16 + (lane >> 2);
                a[mf][0] = __float_as_uint(As[rb][acol]);
                a[mf][1] = __float_as_uint(As[rb + 8][acol]);
                a[mf][2] = __float_as_uint(As[rb][acol + 4]);
                a[mf][3] = __float_as_uint(As[rb + 8][acol + 4]);
            }
            int brow = (lane & 3) + ks * 8;
            #pragma unroll
            for (int nf = 0; nf < 4; nf++) {
                int bn = wn * 32 + nf * 8 + (lane >> 2);
                uint32_t b0 = __float_as_uint(Bs[brow][bn]);
                uint32_t b1 = __float_as_uint(Bs[brow + 4][bn]);
                #pragma unroll
                for (int mf = 0; mf < 2; mf++) {
                    asm volatile(
                        "mma.sync.aligned.m16n8k8.row.col.f32.tf32.tf32.f32 "
                        "{%0,%1,%2,%3}, {%4,%5,%6,%7}, {%8,%9}, {%0,%1,%2,%3};"
                        : "+f"(acc1[mf][nf][0]), "+f"(acc1[mf][nf][1]),
                          "+f"(acc1[mf][nf][2]), "+f"(acc1[mf][nf][3])
                        : "r"(a[mf][0]), "r"(a[mf][1]), "r"(a[mf][2]), "r"(a[mf][3]),
                          "r"(b0), "r"(b1));
                }
            }
        }
        __syncthreads();
    }
    // epilogue 1: qs = acc1 + qbias (tf32-rounded for stage-2 A-frags)
    #pragma unroll
    for (int mf = 0; mf < 2; mf++)
        #pragma unroll
        for (int rs = 0; rs < 2; rs++) {
            int row = wm * 32 + mf * 16 + rs * 8 + (lane >> 2);
            #pragma unroll
            for (int nf = 0; nf < 4; nf++)
                #pragma unroll
                for (int q = 0; q < 2; q++) {
                    int col = wn * 32 + nf * 8 + 2 * (lane & 3) + q;
                    float qv = acc1[mf][nf][rs * 2 + q] + g_qbias[hh * 64 + col];
                    qs[row][col] = __uint_as_float(to_tf32(qv));
                }
        }
    __syncthreads();

    // qbk (only kbase==0 blocks): qbk[d, hh] = sum_c q[d][c] * bk[64hh+c]
    if (kbase == 0 && tid < 128) {
        int d = dbase + tid;
        if (d < NUM_DST) {
            float s = 0.f;
            #pragma unroll 4
            for (int c = 0; c < 64; c++)
                s += qs[tid][c] * bk[hh * 64 + c];
            g_qbk[d * 2 + hh] = s;
        }
    }

    // ---- stage 2: Pq GEMM (K=64) ----
    for (int i = tid; i < 64 * 128; i += 256) {
        int n = i & 127, c = i >> 7;
        int k = kbase + n;
        float vv = (k < KDIM) ? wk[k * DOUT + hh * 64 + c] : 0.f;
        Bs[c][n] = __uint_as_float(to_tf32(vv));
    }
    __syncthreads();

    float acc[2][8][4];
    #pragma unroll
    for (int mf = 0; mf < 2; mf++)
        #pragma unroll
        for (int nf = 0; nf < 8; nf++)
            #pragma unroll
            for (int r = 0; r < 4; r++) acc[mf][nf][r] = 0.f;

    #pragma unroll
    for (int ks = 0; ks < 8; ks++) {
        int acol = (lane & 3) + ks * 8;
        uint32_t a[2][4];
        #pragma unroll
        for (int mf = 0; mf < 2; mf++) {
            int rb = wm * 32 + mf * 16 + (lane >> 2);
            a[mf][0] = __float_as_uint(qs[rb][acol]);
            a[mf][1] = __float_as_uint(qs[rb + 8][acol]);
            a[mf][2] = __float_as_uint(qs[rb][acol + 4]);
            a[mf][3] = __float_as_uint(qs[rb + 8][acol + 4]);
        }
        int brow = (lane & 3) + ks * 8;
        #pragma unroll
        for (int nf = 0; nf < 8; nf++) {
            int bn = wn * 64 + nf * 8 + (lane >> 2);
            uint32_t b0 = __float_as_uint(Bs[brow][bn]);
            uint32_t b1 = __float_as_uint(Bs[brow + 4][bn]);
            #pragma unroll
            for (int mf = 0; mf < 2; mf++) {
                asm volatile(
                    "mma.sync.aligned.m16n8k8.row.col.f32.tf32.tf32.f32 "
                    "{%0,%1,%2,%3}, {%4,%5,%6,%7}, {%8,%9}, {%0,%1,%2,%3};"
                    : "+f"(acc[mf][nf][0]), "+f"(acc[mf][nf][1]),
                      "+f"(acc[mf][nf][2]), "+f"(acc[mf][nf][3])
                    : "r"(a[mf][0]), "r"(a[mf][1]), "r"(a[mf][2]), "r"(a[mf][3]),
                      "r"(b0), "r"(b1));
            }
        }
    }

    __half* out16 = (__half*)g_Pqh;
    #pragma unroll
    for (int mf = 0; mf < 2; mf++) {
        #pragma unroll
        for (int rs = 0; rs < 2; rs++) {
            int d = dbase + wm * 32 + mf * 16 + rs * 8 + (lane >> 2);
            if (d >= NUM_DST) continue;
            #pragma unroll
            for (int nf = 0; nf < 8; nf++) {
                int k0 = kbase + wn * 64 + nf * 8 + 2 * (lane & 3);
                #pragma unroll
                for (int q = 0; q < 2; q++) {
                    int k = k0 + q;
                    if (k < KDIM)
                        out16[((size_t)d * KDIM + k) * 2 + hh] =
                            __float2half_rn(acc[mf][nf][rs * 2 + q]);
                }
            }
        }
    }
}

// ---------------- kernel 2: per-edge warp (UNCHANGED R12/R13) ----------------
__global__ __launch_bounds__(256) void scoreU_kernel(
    const float* __restrict__ h,   const float* __restrict__ ef,
    const float* __restrict__ dt,  const int*   __restrict__ dst_idx,
    const float* __restrict__ time_w, const float* __restrict__ time_b)
{
    int e = (blockIdx.x * 256 + threadIdx.x) >> 5;
    if (e >= NUM_EDGES) return;
    int lane = threadIdx.x & 31;
    float td = dt[e];
    int d = dst_idx[e];
    const float* __restrict__ hrow  = h + (size_t)(NUM_DST + e) * DN;
    const float* __restrict__ efrow = ef + (size_t)e * DE;
    const int k2 = lane * 2;

    float2 v[NPC];
    #pragma unroll
    for (int it = 0; it < 5; it++) {
        int k = it * 64 + k2;
        float2 t;
        if (k < DN) {
            t = __ldcs((const float2*)(hrow + k));
        } else if (k < DN + DE) {
            t = __ldcs((const float2*)(efrow + (k - DN)));
        } else {
            int t0 = k - DN - DE;
            t.x = __cosf(td * time_w[t0]     + time_b[t0]);
            t.y = __cosf(td * time_w[t0 + 1] + time_b[t0 + 1]);
        }
        v[it] = t;
    }
    {
        int k = 5 * 64 + k2;
        float2 t = make_float2(0.f, 0.f);
        if (k < KDIM) {
            int t0 = k - DN - DE;
            t.x = __cosf(td * time_w[t0]     + time_b[t0]);
            t.y = __cosf(td * time_w[t0 + 1] + time_b[t0 + 1]);
        }
        v[5] = t;
    }

    const __half2* __restrict__ pq = g_Pqh + (size_t)d * KDIM;
    float2 p[NPC][2];
    #pragma unroll
    for (int it = 0; it < 5; it++) {
        uint2 raw = __ldg((const uint2*)(pq + it * 64 + k2));
        p[it][0] = __half22float2(*(__half2*)&raw.x);
        p[it][1] = __half22float2(*(__half2*)&raw.y);
    }
    if (5 * 64 + k2 < KDIM) {
        uint2 raw = __ldg((const uint2*)(pq + 5 * 64 + k2));
        p[5][0] = __half22float2(*(__half2*)&raw.x);
        p[5][1] = __half22float2(*(__half2*)&raw.y);
    } else {
        p[5][0] = make_float2(0.f, 0.f);
        p[5][1] = make_float2(0.f, 0.f);
    }

    float a0 = 0.f, a1 = 0.f;
    #pragma unroll
    for (int it = 0; it < NPC; it++) {
        a0 = fmaf(v[it].x, p[it][0].x, a0);
        a1 = fmaf(v[it].x, p[it][0].y, a1);
        a0 = fmaf(v[it].y, p[it][1].x, a0);
        a1 = fmaf(v[it].y, p[it][1].y, a1);
    }
    #pragma unroll
    for (int off = 16; off > 0; off >>= 1) {
        a0 += __shfl_xor_sync(0xffffffffu, a0, off);
        a1 += __shfl_xor_sync(0xffffffffu, a1, off);
    }
    float2 qbk = *(const float2*)(g_qbk + d * 2);
    float s0 = a0 + g_absum[0] + qbk.x;
    float s1 = a1 + g_absum[1] + qbk.y;
    s0 = s0 > 0.f ? s0 : 0.2f * s0;
    s1 = s1 > 0.f ? s1 : 0.2f * s1;
    float e0 = __expf(fminf(s0, 80.f));
    float e1 = __expf(fminf(s1, 80.f));
    if (lane == 0) {
        asm volatile("red.global.add.v2.f32 [%0], {%1,%2};"
                     :: "l"(g_z + d * 2), "f"(e0), "f"(e1) : "memory");
    }
    float2* __restrict__ Urow = g_U + (size_t)d * KDIM;
    #pragma unroll
    for (int it = 0; it < 5; it++) {
        int k = it * 64 + k2;
        float x0 = v[it].x * e0;
        float y0 = v[it].x * e1;
        float x1 = v[it].y * e0;
        float y1 = v[it].y * e1;
        asm volatile("red.global.add.v4.f32 [%0], {%1,%2,%3,%4};"
                     :: "l"(Urow + k), "f"(x0), "f"(y0), "f"(x1), "f"(y1)
                     : "memory");
    }
    if (5 * 64 + k2 < KDIM) {
        float x0 = v[5].x * e0;
        float y0 = v[5].x * e1;
        float x1 = v[5].y * e0;
        float y1 = v[5].y * e1;
        asm volatile("red.global.add.v4.f32 [%0], {%1,%2,%3,%4};"
                     :: "l"(Urow + 5 * 64 + k2), "f"(x0), "f"(y0), "f"(x1), "f"(y1)
                     : "memory");
    }
}

// ---------------- kernel 3: fused agg+out+LN (UNCHANGED R13 outfused) --------
__global__ __launch_bounds__(256) void outfused_kernel(
    const float* __restrict__ h,    const float* __restrict__ wv,
    const float* __restrict__ bv,   const float* __restrict__ wout,
    const float* __restrict__ bout, const float* __restrict__ ln_g,
    const float* __restrict__ ln_b, float* __restrict__ out)
{
    int dbase = blockIdx.x * 16;
    int t = threadIdx.x;
    int c = t & 127;
    int g = t >> 7;
    int hh = c >> 6;
    __shared__ float sU[16][KDIM * 2];
    __shared__ float sZ[16][2];
    __shared__ float sin[16][DOUT + DN];
    __shared__ float red1[16][4], red2[16][4];

    if (t < 32) {
        int d = t >> 1, j = t & 1;
        sZ[d][j] = g_z[(dbase + d) * 2 + j];
    }
    __syncthreads();
    for (int i = t; i < 16 * KDIM * 2; i += 256) {
        int d = i / (KDIM * 2);
        int j = i - d * (KDIM * 2);
        float z = sZ[d][j & 1];
        float u = ((const float*)(g_U + (size_t)(dbase + d) * KDIM))[j];
        sU[d][j] = (z > 0.f) ? (u / z) : 0.f;
    }
    for (int i = t; i < 16 * DN; i += 256) {
        int d = i / DN, k = i - d * DN;
        sin[d][DOUT + k] = h[(size_t)(dbase + d) * DN + k];
    }
    __syncthreads();

    float acc[8];
    #pragma unroll
    for (int d = 0; d < 8; d++) acc[d] = 0.f;
    #pragma unroll 4
    for (int k = 0; k < KDIM; k++) {
        float w = wv[k * DOUT + c];
        #pragma unroll
        for (int d = 0; d < 8; d++)
            acc[d] = fmaf(sU[g * 8 + d][k * 2 + hh], w, acc[d]);
    }
    float bvc = bv[c];
    #pragma unroll
    for (int d = 0; d < 8; d++)
        sin[g * 8 + d][c] = (sZ[g * 8 + d][hh] > 0.f) ? (acc[d] + bvc) : 0.f;
    __syncthreads();

    float b0 = bout[c];
    float a[8];
    #pragma unroll
    for (int d = 0; d < 8; d++) a[d] = b0;
    #pragma unroll 4
    for (int k = 0; k < DOUT + DN; k++) {
        float w = wout[k * DOUT + c];
        #pragma unroll
        for (int d = 0; d < 8; d++) a[d] = fmaf(sin[g * 8 + d][k], w, a[d]);
    }
    float s1[8], s2[8];
    #pragma unroll
    for (int d = 0; d < 8; d++) {
        a[d] = fmaxf(a[d], 0.f);
        s1[d] = a[d];
        s2[d] = a[d] * a[d];
    }
    #pragma unroll
    for (int off = 16; off > 0; off >>= 1) {
        #pragma unroll
        for (int d = 0; d < 8; d++) {
            s1[d] += __shfl_xor_sync(0xffffffffu, s1[d], off);
            s2[d] += __shfl_xor_sync(0xffffffffu, s2[d], off);
        }
    }
    int warp = (t >> 5) & 3;
    if ((t & 31) == 0) {
        #pragma unroll
        for (int d = 0; d < 8; d++) {
            red1[g * 8 + d][warp] = s1[d];
            red2[g * 8 + d][warp] = s2[d];
        }
    }
    __syncthreads();
    #pragma unroll
    for (int d = 0; d < 8; d++) {
        int dd = g * 8 + d;
        float t1 = red1[dd][0] + red1[dd][1] + red1[dd][2] + red1[dd][3];
        float t2 = red2[dd][0] + red2[dd][1] + red2[dd][2] + red2[dd][3];
        float mu  = t1 * (1.f / DOUT);
        float var = t2 * (1.f / DOUT) - mu * mu;
        out[(size_t)(dbase + dd) * DOUT + c] =
            (a[d] - mu) * rsqrtf(var + 1e-5f) * ln_g[c] + ln_b[c];
    }
}

// ---------------- launch -----------------------------------------------------
extern "C" void kernel_launch(void* const* d_in, const int* in_sizes, int n_in,
                              void* d_out, int out_size)
{
    int off = (n_in >= 18 && in_sizes[4] == 1) ? 1 : 0;
    const float* h        = (const float*)d_in[0];
    const float* ef       = (const float*)d_in[1];
    const float* dt       = (const float*)d_in[2];
    const int*   dst_idx  = (const int*)  d_in[3];
    const float* time_w   = (const float*)d_in[4 + off];
    const float* time_b   = (const float*)d_in[5 + off];
    const float* wq       = (const float*)d_in[6 + off];
    const float* bq       = (const float*)d_in[7 + off];
    const float* wk       = (const float*)d_in[8 + off];
    const float* bk       = (const float*)d_in[9 + off];
    const float* wv       = (const float*)d_in[10 + off];
    const float* bv       = (const float*)d_in[11 + off];
    const float* att_bias = (const float*)d_in[12 + off];
    const float* wout     = (const float*)d_in[13 + off];
    const float* bout     = (const float*)d_in[14 + off];
    const float* ln_g     = (const float*)d_in[15 + off];
    const float* ln_b     = (const float*)d_in[16 + off];
    float* out = (float*)d_out;

    cudaFuncSetAttribute(pqfused_kernel,
                         cudaFuncAttributeMaxDynamicSharedMemorySize, PQ_SMEM);

    init_kernel<<<(U_FLOAT4 + 255) / 256, 256>>>(time_b, wq, bq, att_bias);
    pqfused_kernel<<<dim3((NUM_DST + 127) / 128, (KDIM + 127) / 128, 2),
                     256, PQ_SMEM>>>(h, wq, wk, bk);
    scoreU_kernel<<<NUM_EDGES / 8, 256>>>(h, ef, dt, dst_idx, time_w, time_b);
    outfused_kernel<<<NUM_DST / 16, 256>>>(h, wv, bv, wout, bout, ln_g, ln_b, out);
}

// round 16
// speedup vs baseline: 1.0452x; 1.0452x over previous
#include <cuda_runtime.h>
#include <cuda_fp16.h>
#include <cstdint>

#define NUM_DST   10000
#define NUM_EDGES 600000
#define DN   100
#define DE   172
#define DTF  100
#define DOUT 128
#define KDIM (KD_)             // 372
#define KD_  (DN + DE + DTF)
#define NPC  6                 // k-pair chunks: k = it*64 + lane*2
#define KO   228               // phase-2 K = DOUT + DN

// ---------------- scratch ----------------------------------------------------
__device__ float   g_qnodes[NUM_DST * DOUT];
__device__ float   g_qbk[NUM_DST * 2];
__device__ __half2 g_Pqh[(size_t)NUM_DST * KDIM];   // [d][k] -> (head0, head1) fp16
__device__ float2  g_U[(size_t)NUM_DST * KDIM];     // [d][k] -> (head0, head1) fp32
__device__ float   g_z[NUM_DST * 2];
__device__ float   g_qbias[DOUT];
__device__ float   g_absum[2];

#define U_FLOAT4 ((NUM_DST * KDIM * 2) / 4)   // 1,860,000
#define Z_FLOAT4 ((NUM_DST * 2) / 4)          // 5,000

// outfused v2 dynamic smem layout (floats)
#define UST   376                              // sU inner stride per head
#define SST   232                              // sin row stride
#define RST   132                              // rst row stride
#define OFS_SU   0                             // 16*2*376 = 12032 floats
#define OFS_SIN  (16 * 2 * UST)                // 12032
#define OFS_SZ   (OFS_SIN + 16 * SST)          // 15744
#define OUT2_SMEM ((OFS_SZ + 32) * 4)          // 63104 bytes

__device__ __forceinline__ uint32_t to_tf32(float f) {
    uint32_t r;
    asm("cvt.rna.tf32.f32 %0, %1;" : "=r"(r) : "f"(f));
    return r;
}

// ---------------- kernel 0: init (vectorized zero) + derived constants -------
__global__ void init_kernel(const float* __restrict__ time_b,
                            const float* __restrict__ wq,
                            const float* __restrict__ bq,
                            const float* __restrict__ att_bias)
{
    int idx = blockIdx.x * blockDim.x + threadIdx.x;
    float4 zero4 = make_float4(0.f, 0.f, 0.f, 0.f);
    if (idx < U_FLOAT4) ((float4*)g_U)[idx] = zero4;
    if (idx < Z_FLOAT4) ((float4*)g_z)[idx] = zero4;
    if (idx < DOUT) {
        float acc = bq[idx];
        #pragma unroll 4
        for (int t = 0; t < DTF; t++)
            acc += cosf(time_b[t]) * wq[(DN + t) * DOUT + idx];
        g_qbias[idx] = acc;
    }
    if (idx < 2) {
        float s = 0.f;
        for (int j = 0; j < DOUT / 2; j++) s += att_bias[idx * (DOUT / 2) + j];
        g_absum[idx] = s;
    }
}

// ---------------- kernel 1: Q per dst node (8 dst / block) + Q.bk ------------
__global__ __launch_bounds__(128) void qnode_kernel(const float* __restrict__ h,
                                                    const float* __restrict__ wq,
                                                    const float* __restrict__ bk)
{
    int dbase = blockIdx.x * 8;
    int c = threadIdx.x;
    __shared__ float sh[8][DN];
    __shared__ float part[8][4];
    for (int i = c; i < 8 * DN; i += 128) {
        int dl = i / DN, k = i - dl * DN;
        sh[dl][k] = h[(size_t)(dbase + dl) * DN + k];
    }
    __syncthreads();
    float qb = g_qbias[c];
    float a[8];
    #pragma unroll
    for (int d = 0; d < 8; d++) a[d] = qb;
    #pragma unroll 4
    for (int k = 0; k < DN; k++) {
        float w = wq[k * DOUT + c];
        #pragma unroll
        for (int d = 0; d < 8; d++) a[d] = fmaf(sh[d][k], w, a[d]);
    }
    #pragma unroll
    for (int d = 0; d < 8; d++)
        g_qnodes[(dbase + d) * DOUT + c] = a[d];

    float bkc = bk[c];
    float p[8];
    #pragma unroll
    for (int d = 0; d < 8; d++) p[d] = a[d] * bkc;
    #pragma unroll
    for (int off = 16; off > 0; off >>= 1)
        #pragma unroll
        for (int d = 0; d < 8; d++)
            p[d] += __shfl_xor_sync(0xffffffffu, p[d], off);
    int warp = c >> 5;
    if ((c & 31) == 0)
        #pragma unroll
        for (int d = 0; d < 8; d++) part[d][warp] = p[d];
    __syncthreads();
    if (c < 16) {
        int d = c >> 1, hh = c & 1;
        g_qbk[(dbase + d) * 2 + hh] = part[d][hh * 2] + part[d][hh * 2 + 1];
    }
}

// ---------------- kernel 1b: Pq via tf32 MMA (UNCHANGED R13) -----------------
__global__ __launch_bounds__(256) void pqmma_kernel(const float* __restrict__ wk)
{
    __shared__ float As[128][68];
    __shared__ float Bs[64][136];
    const int dbase = blockIdx.x * 128;
    const int kbase = blockIdx.y * 128;
    const int hh    = blockIdx.z;
    const int tid  = threadIdx.x;
    const int lane = tid & 31;
    const int wid  = tid >> 5;
    const int wm   = wid & 3;
    const int wn   = wid >> 2;

    for (int i = tid; i < 128 * 64; i += 256) {
        int r = i >> 6, c = i & 63;
        int d = dbase + r;
        float qv = (d < NUM_DST) ? g_qnodes[d * DOUT + hh * 64 + c] : 0.f;
        As[r][c] = __uint_as_float(to_tf32(qv));
    }
    for (int i = tid; i < 128 * 64; i += 256) {
        int n = i >> 6, c = i & 63;
        int k = kbase + n;
        float wv_ = (k < KDIM) ? wk[k * DOUT + hh * 64 + c] : 0.f;
        Bs[c][n] = __uint_as_float(to_tf32(wv_));
    }
    __syncthreads();

    float acc[2][8][4];
    #pragma unroll
    for (int mf = 0; mf < 2; mf++)
        #pragma unroll
        for (int nf = 0; nf < 8; nf++)
            #pragma unroll
            for (int r = 0; r < 4; r++) acc[mf][nf][r] = 0.f;

    #pragma unroll
    for (int ks = 0; ks < 8; ks++) {
        int acol = (lane & 3) + ks * 8;
        uint32_t a[2][4];
        #pragma unroll
        for (int mf = 0; mf < 2; mf++) {
            int rb = wm * 32 + mf * 16 + (lane >> 2);
            a[mf][0] = __float_as_uint(As[rb][acol]);
            a[mf][1] = __float_as_uint(As[rb + 8][acol]);
            a[mf][2] = __float_as_uint(As[rb][acol + 4]);
            a[mf][3] = __float_as_uint(As[rb + 8][acol + 4]);
        }
        int brow = (lane & 3) + ks * 8;
        #pragma unroll
        for (int nf = 0; nf < 8; nf++) {
            int bn = wn * 64 + nf * 8 + (lane >> 2);
            uint32_t b0 = __float_as_uint(Bs[brow][bn]);
            uint32_t b1 = __float_as_uint(Bs[brow + 4][bn]);
            #pragma unroll
            for (int mf = 0; mf < 2; mf++) {
                asm volatile(
                    "mma.sync.aligned.m16n8k8.row.col.f32.tf32.tf32.f32 "
                    "{%0,%1,%2,%3}, {%4,%5,%6,%7}, {%8,%9}, {%0,%1,%2,%3};"
                    : "+f"(acc[mf][nf][0]), "+f"(acc[mf][nf][1]),
                      "+f"(acc[mf][nf][2]), "+f"(acc[mf][nf][3])
                    : "r"(a[mf][0]), "r"(a[mf][1]), "r"(a[mf][2]), "r"(a[mf][3]),
                      "r"(b0), "r"(b1));
            }
        }
    }

    __half* out16 = (__half*)g_Pqh;
    #pragma unroll
    for (int mf = 0; mf < 2; mf++) {
        #pragma unroll
        for (int rs = 0; rs < 2; rs++) {
            int d = dbase + wm * 32 + mf * 16 + rs * 8 + (lane >> 2);
            if (d >= NUM_DST) continue;
            #pragma unroll
            for (int nf = 0; nf < 8; nf++) {
                int k0 = kbase + wn * 64 + nf * 8 + 2 * (lane & 3);
                #pragma unroll
                for (int q = 0; q < 2; q++) {
                    int k = k0 + q;
                    if (k < KDIM)
                        out16[((size_t)d * KDIM + k) * 2 + hh] =
                            __float2half_rn(acc[mf][nf][rs * 2 + q]);
                }
            }
        }
    }
}

// ---------------- kernel 2: per-edge warp (UNCHANGED R12/R13) ----------------
__global__ __launch_bounds__(256) void scoreU_kernel(
    const float* __restrict__ h,   const float* __restrict__ ef,
    const float* __restrict__ dt,  const int*   __restrict__ dst_idx,
    const float* __restrict__ time_w, const float* __restrict__ time_b)
{
    int e = (blockIdx.x * 256 + threadIdx.x) >> 5;
    if (e >= NUM_EDGES) return;
    int lane = threadIdx.x & 31;
    float td = dt[e];
    int d = dst_idx[e];
    const float* __restrict__ hrow  = h + (size_t)(NUM_DST + e) * DN;
    const float* __restrict__ efrow = ef + (size_t)e * DE;
    const int k2 = lane * 2;

    float2 v[NPC];
    #pragma unroll
    for (int it = 0; it < 5; it++) {
        int k = it * 64 + k2;
        float2 t;
        if (k < DN) {
            t = __ldcs((const float2*)(hrow + k));
        } else if (k < DN + DE) {
            t = __ldcs((const float2*)(efrow + (k - DN)));
        } else {
            int t0 = k - DN - DE;
            t.x = __cosf(td * time_w[t0]     + time_b[t0]);
            t.y = __cosf(td * time_w[t0 + 1] + time_b[t0 + 1]);
        }
        v[it] = t;
    }
    {
        int k = 5 * 64 + k2;
        float2 t = make_float2(0.f, 0.f);
        if (k < KDIM) {
            int t0 = k - DN - DE;
            t.x = __cosf(td * time_w[t0]     + time_b[t0]);
            t.y = __cosf(td * time_w[t0 + 1] + time_b[t0 + 1]);
        }
        v[5] = t;
    }

    const __half2* __restrict__ pq = g_Pqh + (size_t)d * KDIM;
    float2 p[NPC][2];
    #pragma unroll
    for (int it = 0; it < 5; it++) {
        uint2 raw = __ldg((const uint2*)(pq + it * 64 + k2));
        p[it][0] = __half22float2(*(__half2*)&raw.x);
        p[it][1] = __half22float2(*(__half2*)&raw.y);
    }
    if (5 * 64 + k2 < KDIM) {
        uint2 raw = __ldg((const uint2*)(pq + 5 * 64 + k2));
        p[5][0] = __half22float2(*(__half2*)&raw.x);
        p[5][1] = __half22float2(*(__half2*)&raw.y);
    } else {
        p[5][0] = make_float2(0.f, 0.f);
        p[5][1] = make_float2(0.f, 0.f);
    }

    float a0 = 0.f, a1 = 0.f;
    #pragma unroll
    for (int it = 0; it < NPC; it++) {
        a0 = fmaf(v[it].x, p[it][0].x, a0);
        a1 = fmaf(v[it].x, p[it][0].y, a1);
        a0 = fmaf(v[it].y, p[it][1].x, a0);
        a1 = fmaf(v[it].y, p[it][1].y, a1);
    }
    #pragma unroll
    for (int off = 16; off > 0; off >>= 1) {
        a0 += __shfl_xor_sync(0xffffffffu, a0, off);
        a1 += __shfl_xor_sync(0xffffffffu, a1, off);
    }
    float2 qbk = *(const float2*)(g_qbk + d * 2);
    float s0 = a0 + g_absum[0] + qbk.x;
    float s1 = a1 + g_absum[1] + qbk.y;
    s0 = s0 > 0.f ? s0 : 0.2f * s0;
    s1 = s1 > 0.f ? s1 : 0.2f * s1;
    float e0 = __expf(fminf(s0, 80.f));
    float e1 = __expf(fminf(s1, 80.f));
    if (lane == 0) {
        asm volatile("red.global.add.v2.f32 [%0], {%1,%2};"
                     :: "l"(g_z + d * 2), "f"(e0), "f"(e1) : "memory");
    }
    float2* __restrict__ Urow = g_U + (size_t)d * KDIM;
    #pragma unroll
    for (int it = 0; it < 5; it++) {
        int k = it * 64 + k2;
        float x0 = v[it].x * e0;
        float y0 = v[it].x * e1;
        float x1 = v[it].y * e0;
        float y1 = v[it].y * e1;
        asm volatile("red.global.add.v4.f32 [%0], {%1,%2,%3,%4};"
                     :: "l"(Urow + k), "f"(x0), "f"(y0), "f"(x1), "f"(y1)
                     : "memory");
    }
    if (5 * 64 + k2 < KDIM) {
        float x0 = v[5].x * e0;
        float y0 = v[5].x * e1;
        float x1 = v[5].y * e0;
        float y1 = v[5].y * e1;
        asm volatile("red.global.add.v4.f32 [%0], {%1,%2,%3,%4};"
                     :: "l"(Urow + 5 * 64 + k2), "f"(x0), "f"(y0), "f"(x1), "f"(y1)
                     : "memory");
    }
}

// ---------------- kernel 3: outfused v2 — register-tiled, vector LDS ---------
// 16 dst / 256 thr. Thread = 4 dst x 2 cols. sU de-interleaved per head so A
// reads are LDS.128 (4 k). w reads are LDG.64 (2 adjacent cols). rst overlays
// dead sU space; warp-per-row float4 LayerNorm.
__global__ __launch_bounds__(256) void outfused_kernel(
    const float* __restrict__ h,    const float* __restrict__ wv,
    const float* __restrict__ bv,   const float* __restrict__ wout,
    const float* __restrict__ bout, const float* __restrict__ ln_g,
    const float* __restrict__ ln_b, float* __restrict__ out)
{
    extern __shared__ float sm_[];
    float* sU  = sm_ + OFS_SU;    // [16][2][UST]
    float* sin_ = sm_ + OFS_SIN;  // [16][SST]: [0:128)=agg, [128:228)=h
    float* sZ  = sm_ + OFS_SZ;    // [16][2]
    float* rst = sm_ + OFS_SU;    // overlay, [16][RST] (sU dead after phase 1)

    const int dbase = blockIdx.x * 16;
    const int t = threadIdx.x;
    const int cp = t & 63;        // column pair: cols 2cp, 2cp+1
    const int dg = t >> 6;        // dst group: rows 4dg .. 4dg+3
    const int hh = cp >> 5;       // head of both columns
    const int c0 = cp * 2;

    if (t < 32) {
        int d = t >> 1, j = t & 1;
        float z = g_z[(dbase + d) * 2 + j];
        sZ[d * 2 + j] = (z > 0.f) ? (1.f / z) : 0.f;
    }
    __syncthreads();

    // de-interleave U by head, divide by z; pad k=372..375 with 0
    const float* Uflat = (const float*)g_U;
    for (int i = t; i < 16 * KDIM * 2; i += 256) {
        int d = i / (KDIM * 2);
        int j = i - d * (KDIM * 2);
        float rz = sZ[d * 2 + (j & 1)];
        float u = Uflat[(size_t)(dbase + d) * (KDIM * 2) + j];
        sU[(d * 2 + (j & 1)) * UST + (j >> 1)] = u * rz;
    }
    for (int i = t; i < 16 * 2 * 4; i += 256) {
        int d2 = i >> 2;
        sU[d2 * UST + KDIM + (i & 3)] = 0.f;
    }
    // stage h rows for phase 2
    for (int i = t; i < 16 * DN; i += 256) {
        int d = i / DN, k = i - d * DN;
        sin_[d * SST + DOUT + k] = h[(size_t)(dbase + d) * DN + k];
    }
    __syncthreads();

    // ---- phase 1: agg = sU @ wv (per-head slice), tile 4d x 2c ----
    float acc[4][2];
    #pragma unroll
    for (int r = 0; r < 4; r++) { acc[r][0] = 0.f; acc[r][1] = 0.f; }
    {
        const float* su0 = sU + ((dg * 4 + 0) * 2 + hh) * UST;
        const float* su1 = sU + ((dg * 4 + 1) * 2 + hh) * UST;
        const float* su2 = sU + ((dg * 4 + 2) * 2 + hh) * UST;
        const float* su3 = sU + ((dg * 4 + 3) * 2 + hh) * UST;
        #pragma unroll 3
        for (int k4 = 0; k4 < KDIM; k4 += 4) {
            float4 u0 = *(const float4*)(su0 + k4);
            float4 u1 = *(const float4*)(su1 + k4);
            float4 u2 = *(const float4*)(su2 + k4);
            float4 u3 = *(const float4*)(su3 + k4);
            float2 w0 = __ldg((const float2*)(wv + (k4 + 0) * DOUT + c0));
            float2 w1 = __ldg((const float2*)(wv + (k4 + 1) * DOUT + c0));
            float2 w2 = __ldg((const float2*)(wv + (k4 + 2) * DOUT + c0));
            float2 w3 = __ldg((const float2*)(wv + (k4 + 3) * DOUT + c0));
            acc[0][0] += u0.x*w0.x + u0.y*w1.x + u0.z*w2.x + u0.w*w3.x;
            acc[0][1] += u0.x*w0.y + u0.y*w1.y + u0.z*w2.y + u0.w*w3.y;
            acc[1][0] += u1.x*w0.x + u1.y*w1.x + u1.z*w2.x + u1.w*w3.x;
            acc[1][1] += u1.x*w0.y + u1.y*w1.y + u1.z*w2.y + u1.w*w3.y;
            acc[2][0] += u2.x*w0.x + u2.y*w1.x + u2.z*w2.x + u2.w*w3.x;
            acc[2][1] += u2.x*w0.y + u2.y*w1.y + u2.z*w2.y + u2.w*w3.y;
            acc[3][0] += u3.x*w0.x + u3.y*w1.x + u3.z*w2.x + u3.w*w3.x;
            acc[3][1] += u3.x*w0.y + u3.y*w1.y + u3.z*w2.y + u3.w*w3.y;
        }
    }
    float bv0 = __ldg(bv + c0), bv1 = __ldg(bv + c0 + 1);
    #pragma unroll
    for (int r = 0; r < 4; r++) {
        int d = dg * 4 + r;
        bool zg = sZ[d * 2 + hh] > 0.f;
        sin_[d * SST + c0]     = zg ? (acc[r][0] + bv0) : 0.f;
        sin_[d * SST + c0 + 1] = zg ? (acc[r][1] + bv1) : 0.f;
    }
    __syncthreads();

    // ---- phase 2: rst = relu([agg|h] @ wout + bout), tile 4d x 2c ----
    #pragma unroll
    for (int r = 0; r < 4; r++) { acc[r][0] = 0.f; acc[r][1] = 0.f; }
    {
        const float* s0 = sin_ + (dg * 4 + 0) * SST;
        const float* s1 = sin_ + (dg * 4 + 1) * SST;
        const float* s2 = sin_ + (dg * 4 + 2) * SST;
        const float* s3 = sin_ + (dg * 4 + 3) * SST;
        #pragma unroll 3
        for (int k4 = 0; k4 < KO; k4 += 4) {
            float4 u0 = *(const float4*)(s0 + k4);
            float4 u1 = *(const float4*)(s1 + k4);
            float4 u2 = *(const float4*)(s2 + k4);
            float4 u3 = *(const float4*)(s3 + k4);
            float2 w0 = __ldg((const float2*)(wout + (k4 + 0) * DOUT + c0));
            float2 w1 = __ldg((const float2*)(wout + (k4 + 1) * DOUT + c0));
            float2 w2 = __ldg((const float2*)(wout + (k4 + 2) * DOUT + c0));
            float2 w3 = __ldg((const float2*)(wout + (k4 + 3) * DOUT + c0));
            acc[0][0] += u0.x*w0.x + u0.y*w1.x + u0.z*w2.x + u0.w*w3.x;
            acc[0][1] += u0.x*w0.y + u0.y*w1.y + u0.z*w2.y + u0.w*w3.y;
            acc[1][0] += u1.x*w0.x + u1.y*w1.x + u1.z*w2.x + u1.w*w3.x;
            acc[1][1] += u1.x*w0.y + u1.y*w1.y + u1.z*w2.y + u1.w*w3.y;
            acc[2][0] += u2.x*w0.x + u2.y*w1.x + u2.z*w2.x + u2.w*w3.x;
            acc[2][1] += u2.x*w0.y + u2.y*w1.y + u2.z*w2.y + u2.w*w3.y;
            acc[3][0] += u3.x*w0.x + u3.y*w1.x + u3.z*w2.x + u3.w*w3.x;
            acc[3][1] += u3.x*w0.y + u3.y*w1.y + u3.z*w2.y + u3.w*w3.y;
        }
    }
    __syncthreads();   // sin reads done before rst overlay writes? (rst aliases sU, not sin — but keep order strict)
    float bo0 = __ldg(bout + c0), bo1 = __ldg(bout + c0 + 1);
    #pragma unroll
    for (int r = 0; r < 4; r++) {
        int d = dg * 4 + r;
        rst[d * RST + c0]     = fmaxf(acc[r][0] + bo0, 0.f);
        rst[d * RST + c0 + 1] = fmaxf(acc[r][1] + bo1, 0.f);
    }
    __syncthreads();

    // ---- LayerNorm: warp wid -> rows 2*wid, 2*wid+1 ----
    const int lane = t & 31;
    const int wid  = t >> 5;
    float4 lg = *(const float4*)(ln_g + lane * 4);
    float4 lb = *(const float4*)(ln_b + lane * 4);
    #pragma unroll
    for (int r0 = 0; r0 < 2; r0++) {
        int r = wid * 2 + r0;
        float4 x = *(float4*)&rst[r * RST + lane * 4];
        float s1 = x.x + x.y + x.z + x.w;
        float s2 = x.x * x.x + x.y * x.y + x.z * x.z + x.w * x.w;
        #pragma unroll
        for (int off = 16; off > 0; off >>= 1) {
            s1 += __shfl_xor_sync(0xffffffffu, s1, off);
            s2 += __shfl_xor_sync(0xffffffffu, s2, off);
        }
        float mu  = s1 * (1.f / DOUT);
        float var = s2 * (1.f / DOUT) - mu * mu;
        float rstd = rsqrtf(var + 1e-5f);
        float4 o;
        o.x = (x.x - mu) * rstd * lg.x + lb.x;
        o.y = (x.y - mu) * rstd * lg.y + lb.y;
        o.z = (x.z - mu) * rstd * lg.z + lb.z;
        o.w = (x.w - mu) * rstd * lg.w + lb.w;
        *(float4*)(out + (size_t)(dbase + r) * DOUT + lane * 4) = o;
    }
}

// ---------------- launch -----------------------------------------------------
extern "C" void kernel_launch(void* const* d_in, const int* in_sizes, int n_in,
                              void* d_out, int out_size)
{
    int off = (n_in >= 18 && in_sizes[4] == 1) ? 1 : 0;
    const float* h        = (const float*)d_in[0];
    const float* ef       = (const float*)d_in[1];
    const float* dt       = (const float*)d_in[2];
    const int*   dst_idx  = (const int*)  d_in[3];
    const float* time_w   = (const float*)d_in[4 + off];
    const float* time_b   = (const float*)d_in[5 + off];
    const float* wq       = (const float*)d_in[6 + off];
    const float* bq       = (const float*)d_in[7 + off];
    const float* wk       = (const float*)d_in[8 + off];
    const float* bk       = (const float*)d_in[9 + off];
    const float* wv       = (const float*)d_in[10 + off];
    const float* bv       = (const float*)d_in[11 + off];
    const float* att_bias = (const float*)d_in[12 + off];
    const float* wout     = (const float*)d_in[13 + off];
    const float* bout     = (const float*)d_in[14 + off];
    const float* ln_g     = (const float*)d_in[15 + off];
    const float* ln_b     = (const float*)d_in[16 + off];
    float* out = (float*)d_out;

    cudaFuncSetAttribute(outfused_kernel,
                         cudaFuncAttributeMaxDynamicSharedMemorySize, OUT2_SMEM);

    init_kernel<<<(U_FLOAT4 + 255) / 256, 256>>>(time_b, wq, bq, att_bias);
    qnode_kernel<<<NUM_DST / 8, 128>>>(h, wq, bk);
    pqmma_kernel<<<dim3((NUM_DST + 127) / 128, (KDIM + 127) / 128, 2), 256>>>(wk);
    scoreU_kernel<<<NUM_EDGES / 8, 256>>>(h, ef, dt, dst_idx, time_w, time_b);
    outfused_kernel<<<NUM_DST / 16, 256, OUT2_SMEM>>>(
        h, wv, bv, wout, bout, ln_g, ln_b, out);
}

// round 17
// speedup vs baseline: 1.0538x; 1.0082x over previous
#include <cuda_runtime.h>
#include <cuda_fp16.h>
#include <cstdint>

#define NUM_DST   10000
#define NUM_EDGES 600000
#define DN   100
#define DE   172
#define DTF  100
#define DOUT 128
#define KDIM (KD_)             // 372
#define KD_  (DN + DE + DTF)
#define NPC  6                 // k-pair chunks: k = it*64 + lane*2
#define KO   228               // phase-2 K = DOUT + DN

// ---------------- scratch ----------------------------------------------------
__device__ float   g_qnodes[NUM_DST * DOUT];
__device__ float   g_qbk[NUM_DST * 2];
__device__ __half2 g_Pqh[(size_t)NUM_DST * KDIM];   // [d][k] -> (head0, head1) fp16
__device__ float2  g_U[(size_t)NUM_DST * KDIM];     // [d][k] -> (head0, head1) fp32
__device__ float   g_z[NUM_DST * 2];
__device__ float   g_qbias[DOUT];
__device__ float   g_absum[2];

#define U_FLOAT4 ((NUM_DST * KDIM * 2) / 4)   // 1,860,000
#define Z_FLOAT4 ((NUM_DST * 2) / 4)          // 5,000

// outfused v2 dynamic smem layout (floats)
#define UST   376                              // sU inner stride per head
#define SST   232                              // sin row stride
#define RST   132                              // rst row stride
#define OFS_SU   0                             // 16*2*376 = 12032 floats
#define OFS_SIN  (16 * 2 * UST)                // 12032
#define OFS_SZ   (OFS_SIN + 16 * SST)          // 15744
#define OUT2_SMEM ((OFS_SZ + 32) * 4)          // 63104 bytes

__device__ __forceinline__ uint32_t to_tf32(float f) {
    uint32_t r;
    asm("cvt.rna.tf32.f32 %0, %1;" : "=r"(r) : "f"(f));
    return r;
}

// ---------------- kernel 0: init (vectorized zero) + derived constants -------
__global__ void init_kernel(const float* __restrict__ time_b,
                            const float* __restrict__ wq,
                            const float* __restrict__ bq,
                            const float* __restrict__ att_bias)
{
    int idx = blockIdx.x * blockDim.x + threadIdx.x;
    float4 zero4 = make_float4(0.f, 0.f, 0.f, 0.f);
    if (idx < U_FLOAT4) ((float4*)g_U)[idx] = zero4;
    if (idx < Z_FLOAT4) ((float4*)g_z)[idx] = zero4;
    if (idx < DOUT) {
        float acc = bq[idx];
        #pragma unroll 4
        for (int t = 0; t < DTF; t++)
            acc += cosf(time_b[t]) * wq[(DN + t) * DOUT + idx];
        g_qbias[idx] = acc;
    }
    if (idx < 2) {
        float s = 0.f;
        for (int j = 0; j < DOUT / 2; j++) s += att_bias[idx * (DOUT / 2) + j];
        g_absum[idx] = s;
    }
}

// ---------------- kernel 1: Q per dst node (8 dst / block) + Q.bk ------------
__global__ __launch_bounds__(128) void qnode_kernel(const float* __restrict__ h,
                                                    const float* __restrict__ wq,
                                                    const float* __restrict__ bk)
{
    int dbase = blockIdx.x * 8;
    int c = threadIdx.x;
    __shared__ float sh[8][DN];
    __shared__ float part[8][4];
    for (int i = c; i < 8 * DN; i += 128) {
        int dl = i / DN, k = i - dl * DN;
        sh[dl][k] = h[(size_t)(dbase + dl) * DN + k];
    }
    __syncthreads();
    float qb = g_qbias[c];
    float a[8];
    #pragma unroll
    for (int d = 0; d < 8; d++) a[d] = qb;
    #pragma unroll 4
    for (int k = 0; k < DN; k++) {
        float w = wq[k * DOUT + c];
        #pragma unroll
        for (int d = 0; d < 8; d++) a[d] = fmaf(sh[d][k], w, a[d]);
    }
    #pragma unroll
    for (int d = 0; d < 8; d++)
        g_qnodes[(dbase + d) * DOUT + c] = a[d];

    float bkc = bk[c];
    float p[8];
    #pragma unroll
    for (int d = 0; d < 8; d++) p[d] = a[d] * bkc;
    #pragma unroll
    for (int off = 16; off > 0; off >>= 1)
        #pragma unroll
        for (int d = 0; d < 8; d++)
            p[d] += __shfl_xor_sync(0xffffffffu, p[d], off);
    int warp = c >> 5;
    if ((c & 31) == 0)
        #pragma unroll
        for (int d = 0; d < 8; d++) part[d][warp] = p[d];
    __syncthreads();
    if (c < 16) {
        int d = c >> 1, hh = c & 1;
        g_qbk[(dbase + d) * 2 + hh] = part[d][hh * 2] + part[d][hh * 2 + 1];
    }
}

// ---------------- kernel 1b: Pq via tf32 MMA (UNCHANGED R13) -----------------
__global__ __launch_bounds__(256) void pqmma_kernel(const float* __restrict__ wk)
{
    __shared__ float As[128][68];
    __shared__ float Bs[64][136];
    const int dbase = blockIdx.x * 128;
    const int kbase = blockIdx.y * 128;
    const int hh    = blockIdx.z;
    const int tid  = threadIdx.x;
    const int lane = tid & 31;
    const int wid  = tid >> 5;
    const int wm   = wid & 3;
    const int wn   = wid >> 2;

    for (int i = tid; i < 128 * 64; i += 256) {
        int r = i >> 6, c = i & 63;
        int d = dbase + r;
        float qv = (d < NUM_DST) ? g_qnodes[d * DOUT + hh * 64 + c] : 0.f;
        As[r][c] = __uint_as_float(to_tf32(qv));
    }
    for (int i = tid; i < 128 * 64; i += 256) {
        int n = i >> 6, c = i & 63;
        int k = kbase + n;
        float wv_ = (k < KDIM) ? wk[k * DOUT + hh * 64 + c] : 0.f;
        Bs[c][n] = __uint_as_float(to_tf32(wv_));
    }
    __syncthreads();

    float acc[2][8][4];
    #pragma unroll
    for (int mf = 0; mf < 2; mf++)
        #pragma unroll
        for (int nf = 0; nf < 8; nf++)
            #pragma unroll
            for (int r = 0; r < 4; r++) acc[mf][nf][r] = 0.f;

    #pragma unroll
    for (int ks = 0; ks < 8; ks++) {
        int acol = (lane & 3) + ks * 8;
        uint32_t a[2][4];
        #pragma unroll
        for (int mf = 0; mf < 2; mf++) {
            int rb = wm * 32 + mf * 16 + (lane >> 2);
            a[mf][0] = __float_as_uint(As[rb][acol]);
            a[mf][1] = __float_as_uint(As[rb + 8][acol]);
            a[mf][2] = __float_as_uint(As[rb][acol + 4]);
            a[mf][3] = __float_as_uint(As[rb + 8][acol + 4]);
        }
        int brow = (lane & 3) + ks * 8;
        #pragma unroll
        for (int nf = 0; nf < 8; nf++) {
            int bn = wn * 64 + nf * 8 + (lane >> 2);
            uint32_t b0 = __float_as_uint(Bs[brow][bn]);
            uint32_t b1 = __float_as_uint(Bs[brow + 4][bn]);
            #pragma unroll
            for (int mf = 0; mf < 2; mf++) {
                asm volatile(
                    "mma.sync.aligned.m16n8k8.row.col.f32.tf32.tf32.f32 "
                    "{%0,%1,%2,%3}, {%4,%5,%6,%7}, {%8,%9}, {%0,%1,%2,%3};"
                    : "+f"(acc[mf][nf][0]), "+f"(acc[mf][nf][1]),
                      "+f"(acc[mf][nf][2]), "+f"(acc[mf][nf][3])
                    : "r"(a[mf][0]), "r"(a[mf][1]), "r"(a[mf][2]), "r"(a[mf][3]),
                      "r"(b0), "r"(b1));
            }
        }
    }

    __half* out16 = (__half*)g_Pqh;
    #pragma unroll
    for (int mf = 0; mf < 2; mf++) {
        #pragma unroll
        for (int rs = 0; rs < 2; rs++) {
            int d = dbase + wm * 32 + mf * 16 + rs * 8 + (lane >> 2);
            if (d >= NUM_DST) continue;
            #pragma unroll
            for (int nf = 0; nf < 8; nf++) {
                int k0 = kbase + wn * 64 + nf * 8 + 2 * (lane & 3);
                #pragma unroll
                for (int q = 0; q < 2; q++) {
                    int k = k0 + q;
                    if (k < KDIM)
                        out16[((size_t)d * KDIM + k) * 2 + hh] =
                            __float2half_rn(acc[mf][nf][rs * 2 + q]);
                }
            }
        }
    }
}

// ---------------- kernel 2: per-edge warp (UNCHANGED R12/R13) ----------------
__global__ __launch_bounds__(256) void scoreU_kernel(
    const float* __restrict__ h,   const float* __restrict__ ef,
    const float* __restrict__ dt,  const int*   __restrict__ dst_idx,
    const float* __restrict__ time_w, const float* __restrict__ time_b)
{
    int e = (blockIdx.x * 256 + threadIdx.x) >> 5;
    if (e >= NUM_EDGES) return;
    int lane = threadIdx.x & 31;
    float td = dt[e];
    int d = dst_idx[e];
    const float* __restrict__ hrow  = h + (size_t)(NUM_DST + e) * DN;
    const float* __restrict__ efrow = ef + (size_t)e * DE;
    const int k2 = lane * 2;

    float2 v[NPC];
    #pragma unroll
    for (int it = 0; it < 5; it++) {
        int k = it * 64 + k2;
        float2 t;
        if (k < DN) {
            t = __ldcs((const float2*)(hrow + k));
        } else if (k < DN + DE) {
            t = __ldcs((const float2*)(efrow + (k - DN)));
        } else {
            int t0 = k - DN - DE;
            t.x = __cosf(td * time_w[t0]     + time_b[t0]);
            t.y = __cosf(td * time_w[t0 + 1] + time_b[t0 + 1]);
        }
        v[it] = t;
    }
    {
        int k = 5 * 64 + k2;
        float2 t = make_float2(0.f, 0.f);
        if (k < KDIM) {
            int t0 = k - DN - DE;
            t.x = __cosf(td * time_w[t0]     + time_b[t0]);
            t.y = __cosf(td * time_w[t0 + 1] + time_b[t0 + 1]);
        }
        v[5] = t;
    }

    const __half2* __restrict__ pq = g_Pqh + (size_t)d * KDIM;
    float2 p[NPC][2];
    #pragma unroll
    for (int it = 0; it < 5; it++) {
        uint2 raw = __ldg((const uint2*)(pq + it * 64 + k2));
        p[it][0] = __half22float2(*(__half2*)&raw.x);
        p[it][1] = __half22float2(*(__half2*)&raw.y);
    }
    if (5 * 64 + k2 < KDIM) {
        uint2 raw = __ldg((const uint2*)(pq + 5 * 64 + k2));
        p[5][0] = __half22float2(*(__half2*)&raw.x);
        p[5][1] = __half22float2(*(__half2*)&raw.y);
    } else {
        p[5][0] = make_float2(0.f, 0.f);
        p[5][1] = make_float2(0.f, 0.f);
    }

    float a0 = 0.f, a1 = 0.f;
    #pragma unroll
    for (int it = 0; it < NPC; it++) {
        a0 = fmaf(v[it].x, p[it][0].x, a0);
        a1 = fmaf(v[it].x, p[it][0].y, a1);
        a0 = fmaf(v[it].y, p[it][1].x, a0);
        a1 = fmaf(v[it].y, p[it][1].y, a1);
    }
    #pragma unroll
    for (int off = 16; off > 0; off >>= 1) {
        a0 += __shfl_xor_sync(0xffffffffu, a0, off);
        a1 += __shfl_xor_sync(0xffffffffu, a1, off);
    }
    float2 qbk = *(const float2*)(g_qbk + d * 2);
    float s0 = a0 + g_absum[0] + qbk.x;
    float s1 = a1 + g_absum[1] + qbk.y;
    s0 = s0 > 0.f ? s0 : 0.2f * s0;
    s1 = s1 > 0.f ? s1 : 0.2f * s1;
    float e0 = __expf(fminf(s0, 80.f));
    float e1 = __expf(fminf(s1, 80.f));
    if (lane == 0) {
        asm volatile("red.global.add.v2.f32 [%0], {%1,%2};"
                     :: "l"(g_z + d * 2), "f"(e0), "f"(e1) : "memory");
    }
    float2* __restrict__ Urow = g_U + (size_t)d * KDIM;
    #pragma unroll
    for (int it = 0; it < 5; it++) {
        int k = it * 64 + k2;
        float x0 = v[it].x * e0;
        float y0 = v[it].x * e1;
        float x1 = v[it].y * e0;
        float y1 = v[it].y * e1;
        asm volatile("red.global.add.v4.f32 [%0], {%1,%2,%3,%4};"
                     :: "l"(Urow + k), "f"(x0), "f"(y0), "f"(x1), "f"(y1)
                     : "memory");
    }
    if (5 * 64 + k2 < KDIM) {
        float x0 = v[5].x * e0;
        float y0 = v[5].x * e1;
        float x1 = v[5].y * e0;
        float y1 = v[5].y * e1;
        asm volatile("red.global.add.v4.f32 [%0], {%1,%2,%3,%4};"
                     :: "l"(Urow + 5 * 64 + k2), "f"(x0), "f"(y0), "f"(x1), "f"(y1)
                     : "memory");
    }
}

// ---------------- kernel 3: outfused v2 — register-tiled, vector LDS ---------
// 16 dst / 256 thr. Thread = 4 dst x 2 cols. sU de-interleaved per head so A
// reads are LDS.128 (4 k). w reads are LDG.64 (2 adjacent cols). rst overlays
// dead sU space; warp-per-row float4 LayerNorm.
__global__ __launch_bounds__(256) void outfused_kernel(
    const float* __restrict__ h,    const float* __restrict__ wv,
    const float* __restrict__ bv,   const float* __restrict__ wout,
    const float* __restrict__ bout, const float* __restrict__ ln_g,
    const float* __restrict__ ln_b, float* __restrict__ out)
{
    extern __shared__ float sm_[];
    float* sU  = sm_ + OFS_SU;    // [16][2][UST]
    float* sin_ = sm_ + OFS_SIN;  // [16][SST]: [0:128)=agg, [128:228)=h
    float* sZ  = sm_ + OFS_SZ;    // [16][2]
    float* rst = sm_ + OFS_SU;    // overlay, [16][RST] (sU dead after phase 1)

    const int dbase = blockIdx.x * 16;
    const int t = threadIdx.x;
    const int cp = t & 63;        // column pair: cols 2cp, 2cp+1
    const int dg = t >> 6;        // dst group: rows 4dg .. 4dg+3
    const int hh = cp >> 5;       // head of both columns
    const int c0 = cp * 2;

    if (t < 32) {
        int d = t >> 1, j = t & 1;
        float z = g_z[(dbase + d) * 2 + j];
        sZ[d * 2 + j] = (z > 0.f) ? (1.f / z) : 0.f;
    }
    __syncthreads();

    // de-interleave U by head, divide by z; pad k=372..375 with 0
    const float* Uflat = (const float*)g_U;
    for (int i = t; i < 16 * KDIM * 2; i += 256) {
        int d = i / (KDIM * 2);
        int j = i - d * (KDIM * 2);
        float rz = sZ[d * 2 + (j & 1)];
        float u = Uflat[(size_t)(dbase + d) * (KDIM * 2) + j];
        sU[(d * 2 + (j & 1)) * UST + (j >> 1)] = u * rz;
    }
    for (int i = t; i < 16 * 2 * 4; i += 256) {
        int d2 = i >> 2;
        sU[d2 * UST + KDIM + (i & 3)] = 0.f;
    }
    // stage h rows for phase 2
    for (int i = t; i < 16 * DN; i += 256) {
        int d = i / DN, k = i - d * DN;
        sin_[d * SST + DOUT + k] = h[(size_t)(dbase + d) * DN + k];
    }
    __syncthreads();

    // ---- phase 1: agg = sU @ wv (per-head slice), tile 4d x 2c ----
    float acc[4][2];
    #pragma unroll
    for (int r = 0; r < 4; r++) { acc[r][0] = 0.f; acc[r][1] = 0.f; }
    {
        const float* su0 = sU + ((dg * 4 + 0) * 2 + hh) * UST;
        const float* su1 = sU + ((dg * 4 + 1) * 2 + hh) * UST;
        const float* su2 = sU + ((dg * 4 + 2) * 2 + hh) * UST;
        const float* su3 = sU + ((dg * 4 + 3) * 2 + hh) * UST;
        #pragma unroll 3
        for (int k4 = 0; k4 < KDIM; k4 += 4) {
            float4 u0 = *(const float4*)(su0 + k4);
            float4 u1 = *(const float4*)(su1 + k4);
            float4 u2 = *(const float4*)(su2 + k4);
            float4 u3 = *(const float4*)(su3 + k4);
            float2 w0 = __ldg((const float2*)(wv + (k4 + 0) * DOUT + c0));
            float2 w1 = __ldg((const float2*)(wv + (k4 + 1) * DOUT + c0));
            float2 w2 = __ldg((const float2*)(wv + (k4 + 2) * DOUT + c0));
            float2 w3 = __ldg((const float2*)(wv + (k4 + 3) * DOUT + c0));
            acc[0][0] += u0.x*w0.x + u0.y*w1.x + u0.z*w2.x + u0.w*w3.x;
            acc[0][1] += u0.x*w0.y + u0.y*w1.y + u0.z*w2.y + u0.w*w3.y;
            acc[1][0] += u1.x*w0.x + u1.y*w1.x + u1.z*w2.x + u1.w*w3.x;
            acc[1][1] += u1.x*w0.y + u1.y*w1.y + u1.z*w2.y + u1.w*w3.y;
            acc[2][0] += u2.x*w0.x + u2.y*w1.x + u2.z*w2.x + u2.w*w3.x;
            acc[2][1] += u2.x*w0.y + u2.y*w1.y + u2.z*w2.y + u2.w*w3.y;
            acc[3][0] += u3.x*w0.x + u3.y*w1.x + u3.z*w2.x + u3.w*w3.x;
            acc[3][1] += u3.x*w0.y + u3.y*w1.y + u3.z*w2.y + u3.w*w3.y;
        }
    }
    float bv0 = __ldg(bv + c0), bv1 = __ldg(bv + c0 + 1);
    #pragma unroll
    for (int r = 0; r < 4; r++) {
        int d = dg * 4 + r;
        bool zg = sZ[d * 2 + hh] > 0.f;
        sin_[d * SST + c0]     = zg ? (acc[r][0] + bv0) : 0.f;
        sin_[d * SST + c0 + 1] = zg ? (acc[r][1] + bv1) : 0.f;
    }
    __syncthreads();

    // ---- phase 2: rst = relu([agg|h] @ wout + bout), tile 4d x 2c ----
    #pragma unroll
    for (int r = 0; r < 4; r++) { acc[r][0] = 0.f; acc[r][1] = 0.f; }
    {
        const float* s0 = sin_ + (dg * 4 + 0) * SST;
        const float* s1 = sin_ + (dg * 4 + 1) * SST;
        const float* s2 = sin_ + (dg * 4 + 2) * SST;
        const float* s3 = sin_ + (dg * 4 + 3) * SST;
        #pragma unroll 3
        for (int k4 = 0; k4 < KO; k4 += 4) {
            float4 u0 = *(const float4*)(s0 + k4);
            float4 u1 = *(const float4*)(s1 + k4);
            float4 u2 = *(const float4*)(s2 + k4);
            float4 u3 = *(const float4*)(s3 + k4);
            float2 w0 = __ldg((const float2*)(wout + (k4 + 0) * DOUT + c0));
            float2 w1 = __ldg((const float2*)(wout + (k4 + 1) * DOUT + c0));
            float2 w2 = __ldg((const float2*)(wout + (k4 + 2) * DOUT + c0));
            float2 w3 = __ldg((const float2*)(wout + (k4 + 3) * DOUT + c0));
            acc[0][0] += u0.x*w0.x + u0.y*w1.x + u0.z*w2.x + u0.w*w3.x;
            acc[0][1] += u0.x*w0.y + u0.y*w1.y + u0.z*w2.y + u0.w*w3.y;
            acc[1][0] += u1.x*w0.x + u1.y*w1.x + u1.z*w2.x + u1.w*w3.x;
            acc[1][1] += u1.x*w0.y + u1.y*w1.y + u1.z*w2.y + u1.w*w3.y;
            acc[2][0] += u2.x*w0.x + u2.y*w1.x + u2.z*w2.x + u2.w*w3.x;
            acc[2][1] += u2.x*w0.y + u2.y*w1.y + u2.z*w2.y + u2.w*w3.y;
            acc[3][0] += u3.x*w0.x + u3.y*w1.x + u3.z*w2.x + u3.w*w3.x;
            acc[3][1] += u3.x*w0.y + u3.y*w1.y + u3.z*w2.y + u3.w*w3.y;
        }
    }
    __syncthreads();   // sin reads done before rst overlay writes? (rst aliases sU, not sin — but keep order strict)
    float bo0 = __ldg(bout + c0), bo1 = __ldg(bout + c0 + 1);
    #pragma unroll
    for (int r = 0; r < 4; r++) {
        int d = dg * 4 + r;
        rst[d * RST + c0]     = fmaxf(acc[r][0] + bo0, 0.f);
        rst[d * RST + c0 + 1] = fmaxf(acc[r][1] + bo1, 0.f);
    }
    __syncthreads();

    // ---- LayerNorm: warp wid -> rows 2*wid, 2*wid+1 ----
    const int lane = t & 31;
    const int wid  = t >> 5;
    float4 lg = *(const float4*)(ln_g + lane * 4);
    float4 lb = *(const float4*)(ln_b + lane * 4);
    #pragma unroll
    for (int r0 = 0; r0 < 2; r0++) {
        int r = wid * 2 + r0;
        float4 x = *(float4*)&rst[r * RST + lane * 4];
        float s1 = x.x + x.y + x.z + x.w;
        float s2 = x.x * x.x + x.y * x.y + x.z * x.z + x.w * x.w;
        #pragma unroll
        for (int off = 16; off > 0; off >>= 1) {
            s1 += __shfl_xor_sync(0xffffffffu, s1, off);
            s2 += __shfl_xor_sync(0xffffffffu, s2, off);
        }
        float mu  = s1 * (1.f / DOUT);
        float var = s2 * (1.f / DOUT) - mu * mu;
        float rstd = rsqrtf(var + 1e-5f);
        float4 o;
        o.x = (x.x - mu) * rstd * lg.x + lb.x;
        o.y = (x.y - mu) * rstd * lg.y + lb.y;
        o.z = (x.z - mu) * rstd * lg.z + lb.z;
        o.w = (x.w - mu) * rstd * lg.w + lb.w;
        *(float4*)(out + (size_t)(dbase + r) * DOUT + lane * 4) = o;
    }
}

// ---------------- launch -----------------------------------------------------
extern "C" void kernel_launch(void* const* d_in, const int* in_sizes, int n_in,
                              void* d_out, int out_size)
{
    int off = (n_in >= 18 && in_sizes[4] == 1) ? 1 : 0;
    const float* h        = (const float*)d_in[0];
    const float* ef       = (const float*)d_in[1];
    const float* dt       = (const float*)d_in[2];
    const int*   dst_idx  = (const int*)  d_in[3];
    const float* time_w   = (const float*)d_in[4 + off];
    const float* time_b   = (const float*)d_in[5 + off];
    const float* wq       = (const float*)d_in[6 + off];
    const float* bq       = (const float*)d_in[7 + off];
    const float* wk       = (const float*)d_in[8 + off];
    const float* bk       = (const float*)d_in[9 + off];
    const float* wv       = (const float*)d_in[10 + off];
    const float* bv       = (const float*)d_in[11 + off];
    const float* att_bias = (const float*)d_in[12 + off];
    const float* wout     = (const float*)d_in[13 + off];
    const float* bout     = (const float*)d_in[14 + off];
    const float* ln_g     = (const float*)d_in[15 + off];
    const float* ln_b     = (const float*)d_in[16 + off];
    float* out = (float*)d_out;

    cudaFuncSetAttribute(outfused_kernel,
                         cudaFuncAttributeMaxDynamicSharedMemorySize, OUT2_SMEM);

    init_kernel<<<(U_FLOAT4 + 255) / 256, 256>>>(time_b, wq, bq, att_bias);
    qnode_kernel<<<NUM_DST / 8, 128>>>(h, wq, bk);
    pqmma_kernel<<<dim3((NUM_DST + 127) / 128, (KDIM + 127) / 128, 2), 256>>>(wk);
    scoreU_kernel<<<NUM_EDGES / 8, 256>>>(h, ef, dt, dst_idx, time_w, time_b);
    outfused_kernel<<<NUM_DST / 16, 256, OUT2_SMEM>>>(
        h, wv, bv, wout, bout, ln_g, ln_b, out);
}